// round 3
// baseline (speedup 1.0000x reference)
#include <cuda_runtime.h>
#include <stdint.h>

// ---------------------------------------------------------------------------
// BoltzmannGibbsMask: out = softmax(G / 0.5, axis=1) @ x
//   G = jax.random.normal(jax.random.key(42), (8192, 8192), f32)
// Reproduces JAX threefry2x32 (partitionable path) + XLA ErfInv32 bit-closely.
// Logits 2*m are bounded (|2m| <= ~10.6) -> no max subtraction needed:
//   out[r,:] = (sum_c exp(2*m[r,c]) * x[c,:]) / (sum_c exp(2*m[r,c]))
// ---------------------------------------------------------------------------

namespace {
constexpr int kN       = 8192;   // rows/cols of G
constexpr int kD       = 1024;   // feature dim
constexpr int kRows    = 16;     // rows per CTA
constexpr int kCBlk    = 8;      // columns per tile
constexpr int kThreads = 256;
}

// Threefry-2x32, key = (0, 42)  (jax.random.key(42))
__device__ __forceinline__ void threefry_0_42(uint32_t x0, uint32_t x1,
                                              uint32_t& o0, uint32_t& o1) {
  const uint32_t ks0 = 0u;
  const uint32_t ks1 = 42u;
  const uint32_t ks2 = 0x1BD11BDAu ^ 42u;   // 0x1BD11BF0
  x0 += ks0; x1 += ks1;
#define TF_RND(R) { x0 += x1; x1 = __funnelshift_l(x1, x1, (R)); x1 ^= x0; }
  TF_RND(13) TF_RND(15) TF_RND(26) TF_RND(6)
  x0 += ks1; x1 += ks2 + 1u;
  TF_RND(17) TF_RND(29) TF_RND(16) TF_RND(24)
  x0 += ks2; x1 += ks0 + 2u;
  TF_RND(13) TF_RND(15) TF_RND(26) TF_RND(6)
  x0 += ks0; x1 += ks1 + 3u;
  TF_RND(17) TF_RND(29) TF_RND(16) TF_RND(24)
  x0 += ks1; x1 += ks2 + 4u;
  TF_RND(13) TF_RND(15) TF_RND(26) TF_RND(6)
  x0 += ks2; x1 += ks0 + 5u;
#undef TF_RND
  o0 = x0; o1 = x1;
}

// XLA ErfInv32 (Giles), w = -log1p(-x*x)
__device__ __forceinline__ float erfinv_xla(float x) {
  float w = -log1pf(-x * x);
  float p;
  if (w < 5.0f) {
    w = w - 2.5f;
    p = 2.81022636e-08f;
    p = fmaf(p, w, 3.43273939e-07f);
    p = fmaf(p, w, -3.5233877e-06f);
    p = fmaf(p, w, -4.39150654e-06f);
    p = fmaf(p, w, 0.00021858087f);
    p = fmaf(p, w, -0.00125372503f);
    p = fmaf(p, w, -0.00417768164f);
    p = fmaf(p, w, 0.246640727f);
    p = fmaf(p, w, 1.50140941f);
  } else {
    w = sqrtf(w) - 3.0f;
    p = -0.000200214257f;
    p = fmaf(p, w, 0.000100950558f);
    p = fmaf(p, w, 0.00134934322f);
    p = fmaf(p, w, -0.00367342844f);
    p = fmaf(p, w, 0.00573950773f);
    p = fmaf(p, w, -0.0076224613f);
    p = fmaf(p, w, 0.00943887047f);
    p = fmaf(p, w, 1.00167406f);
    p = fmaf(p, w, 2.83297682f);
  }
  return p * x;
}

// Unnormalized Gibbs weight exp(2 * normal(idx)) for flat index idx into G.
__device__ __forceinline__ float gibbs_weight(uint32_t idx) {
  uint32_t o0, o1;
  threefry_0_42(0u, idx, o0, o1);           // partitionable: counts=(0, idx)
  uint32_t bits = o0 ^ o1;                  // 32-bit fold
  // uniform in [lo, 1): f in [0,1) with 23 random mantissa bits
  float f = __uint_as_float((bits >> 9) | 0x3f800000u);
  f = __fadd_rn(f, -1.0f);                  // exact (Sterbenz)
  const float lo = -0.99999994f;            // nextafter(-1, 0)
  float u = __fadd_rn(__fmul_rn(f, 2.0f), lo);  // (hi-lo) rounds to 2.0f
  u = fmaxf(lo, u);
  float m = 1.41421356237f * erfinv_xla(u); // sqrt(2) * erfinv
  return __expf(__fmul_rn(m, 2.0f));        // exp(m / ALPHA), ALPHA=0.5
}

__global__ void __launch_bounds__(kThreads, 2)
boltzmann_gibbs_kernel(const float* __restrict__ x, float* __restrict__ out) {
  __shared__ float xs[kCBlk * kD];          // staged x tile    (32 KB)
  __shared__ float ps[kCBlk * kRows];       // weight tile P^T  (512 B)
  __shared__ float ls[kRows];               // row sums

  const int t  = threadIdx.x;
  const int d0 = t * 4;                                  // this thread's 4 d-columns
  const uint32_t row0 = (uint32_t)blockIdx.x * kRows;
  const int grow = t >> 3;                               // gen row   (t < 128)
  const int gcol = t & 7;                                // gen col
  const uint32_t gbase = (row0 + (uint32_t)grow) * (uint32_t)kN + (uint32_t)gcol;

  float acc[kRows][4];
#pragma unroll
  for (int r = 0; r < kRows; r++) {
    acc[r][0] = 0.f; acc[r][1] = 0.f; acc[r][2] = 0.f; acc[r][3] = 0.f;
  }
  float rsum = 0.0f;

  for (int cb = 0; cb < kN; cb += kCBlk) {
    // ---- stage x[cb .. cb+8) rows into SMEM (all 256 threads) ----
#pragma unroll
    for (int k = 0; k < kCBlk; k++) {
      float4 v = *(const float4*)(x + (size_t)(cb + k) * kD + d0);
      *(float4*)(xs + k * kD + d0) = v;
    }
    // ---- generate 16x8 weight tile (threads 0..127), overlapped with LDGs ----
    if (t < 128) {
      float p = gibbs_weight(gbase + (uint32_t)cb);
      ps[gcol * kRows + grow] = p;
      rsum += p;
    }
    __syncthreads();

    // ---- rank-1 updates: acc[r][:] += P[r][c] * x[c][d0..d0+3] ----
#pragma unroll
    for (int c = 0; c < kCBlk; c++) {
      const float4 xv = *(const float4*)(xs + c * kD + d0);
      const float4 pa = *(const float4*)(ps + c * kRows + 0);
      const float4 pb = *(const float4*)(ps + c * kRows + 4);
      const float4 pc = *(const float4*)(ps + c * kRows + 8);
      const float4 pd = *(const float4*)(ps + c * kRows + 12);
      const float pr[kRows] = {pa.x, pa.y, pa.z, pa.w, pb.x, pb.y, pb.z, pb.w,
                               pc.x, pc.y, pc.z, pc.w, pd.x, pd.y, pd.z, pd.w};
#pragma unroll
      for (int r = 0; r < kRows; r++) {
        acc[r][0] = fmaf(pr[r], xv.x, acc[r][0]);
        acc[r][1] = fmaf(pr[r], xv.y, acc[r][1]);
        acc[r][2] = fmaf(pr[r], xv.z, acc[r][2]);
        acc[r][3] = fmaf(pr[r], xv.w, acc[r][3]);
      }
    }
    __syncthreads();
  }

  // ---- row-sum reduction: 8 threads per row (within half/quarter warps) ----
  if (t < 128) {
    float s = rsum;
    s += __shfl_xor_sync(0xFFFFFFFFu, s, 1);
    s += __shfl_xor_sync(0xFFFFFFFFu, s, 2);
    s += __shfl_xor_sync(0xFFFFFFFFu, s, 4);
    if (gcol == 0) ls[grow] = s;
  }
  __syncthreads();

  // ---- normalize + store ----
#pragma unroll
  for (int r = 0; r < kRows; r++) {
    const float inv = 1.0f / ls[r];
    float4 o;
    o.x = acc[r][0] * inv;
    o.y = acc[r][1] * inv;
    o.z = acc[r][2] * inv;
    o.w = acc[r][3] * inv;
    *(float4*)(out + (size_t)(row0 + r) * kD + d0) = o;
  }
}

extern "C" void kernel_launch(void* const* d_in, const int* in_sizes, int n_in,
                              void* d_out, int out_size) {
  (void)in_sizes; (void)n_in; (void)out_size;
  const float* x = (const float*)d_in[0];   // [8192, 1024] f32 (edge_index unused)
  float* out = (float*)d_out;               // [8192, 1024] f32
  boltzmann_gibbs_kernel<<<kN / kRows, kThreads>>>(x, out);
}

// round 6
// speedup vs baseline: 3.0370x; 3.0370x over previous
#include <cuda_runtime.h>
#include <stdint.h>

// ---------------------------------------------------------------------------
// BoltzmannGibbsMask: out = softmax(G / 0.5, axis=1) @ x,
//   G = jax.random.normal(jax.random.key(42), (8192, 8192), f32)
// compute_103-portable plan (no 'a'-suffix PTX features):
//   K0: round x to tf32 -> g_xC
//   K1: W[r][c] = tf32(exp(2*normal(r*8192+c))) -> g_W, unrounded row sums
//   K2: mma.sync.m16n8k8 tf32 GEMM, out = (W @ x) / rowsum
// ---------------------------------------------------------------------------

static __device__ float g_W[67108864];   // 8192*8192 f32(tf32-rounded), 256 MB
static __device__ float g_xC[8388608];   // 8192*1024 f32(tf32-rounded), 32 MB
static __device__ float g_rsum[8192];

// ============================ RNG (bit-exact, validated R1) =================
__device__ __forceinline__ void threefry_0_42(uint32_t x0, uint32_t x1,
                                              uint32_t& o0, uint32_t& o1) {
  const uint32_t ks0 = 0u, ks1 = 42u, ks2 = 0x1BD11BDAu ^ 42u;
  x0 += ks0; x1 += ks1;
#define TF_RND(R) { x0 += x1; x1 = __funnelshift_l(x1, x1, (R)); x1 ^= x0; }
  TF_RND(13) TF_RND(15) TF_RND(26) TF_RND(6)
  x0 += ks1; x1 += ks2 + 1u;
  TF_RND(17) TF_RND(29) TF_RND(16) TF_RND(24)
  x0 += ks2; x1 += ks0 + 2u;
  TF_RND(13) TF_RND(15) TF_RND(26) TF_RND(6)
  x0 += ks0; x1 += ks1 + 3u;
  TF_RND(17) TF_RND(29) TF_RND(16) TF_RND(24)
  x0 += ks1; x1 += ks2 + 4u;
  TF_RND(13) TF_RND(15) TF_RND(26) TF_RND(6)
  x0 += ks2; x1 += ks0 + 5u;
#undef TF_RND
  o0 = x0; o1 = x1;
}

__device__ __forceinline__ float erfinv_xla(float x) {
  float w = -log1pf(-x * x);
  float p;
  if (w < 5.0f) {
    w = w - 2.5f;
    p = 2.81022636e-08f;
    p = fmaf(p, w, 3.43273939e-07f);
    p = fmaf(p, w, -3.5233877e-06f);
    p = fmaf(p, w, -4.39150654e-06f);
    p = fmaf(p, w, 0.00021858087f);
    p = fmaf(p, w, -0.00125372503f);
    p = fmaf(p, w, -0.00417768164f);
    p = fmaf(p, w, 0.246640727f);
    p = fmaf(p, w, 1.50140941f);
  } else {
    w = sqrtf(w) - 3.0f;
    p = -0.000200214257f;
    p = fmaf(p, w, 0.000100950558f);
    p = fmaf(p, w, 0.00134934322f);
    p = fmaf(p, w, -0.00367342844f);
    p = fmaf(p, w, 0.00573950773f);
    p = fmaf(p, w, -0.0076224613f);
    p = fmaf(p, w, 0.00943887047f);
    p = fmaf(p, w, 1.00167406f);
    p = fmaf(p, w, 2.83297682f);
  }
  return p * x;
}

__device__ __forceinline__ float gibbs_weight(uint32_t idx) {
  uint32_t o0, o1;
  threefry_0_42(0u, idx, o0, o1);
  uint32_t bits = o0 ^ o1;
  float f = __uint_as_float((bits >> 9) | 0x3f800000u);
  f = __fadd_rn(f, -1.0f);
  const float lo = -0.99999994f;
  float u = __fadd_rn(__fmul_rn(f, 2.0f), lo);
  u = fmaxf(lo, u);
  float m = 1.41421356237f * erfinv_xla(u);
  return __expf(__fmul_rn(m, 2.0f));
}

// ============================ helpers ======================================
__device__ __forceinline__ uint32_t f2tf32(float f) {
  uint32_t r;
  asm("cvt.rna.tf32.f32 %0, %1;" : "=r"(r) : "f"(f));
  return r;
}
__device__ __forceinline__ uint32_t smem_to_u32(const void* p) {
  uint32_t a;
  asm("{ .reg .u64 t; cvta.to.shared.u64 t, %1; cvt.u32.u64 %0, t; }"
      : "=r"(a) : "l"(p));
  return a;
}
#define CP_ASYNC16(dst, src) \
  asm volatile("cp.async.cg.shared.global [%0], [%1], 16;" \
               :: "r"(dst), "l"(src) : "memory")

// ============================ K0: round x to tf32 ===========================
__global__ void __launch_bounds__(256)
xconv_kernel(const float* __restrict__ x) {
  size_t i = ((size_t)blockIdx.x * 256 + threadIdx.x) * 4;
  float4 v = *(const float4*)(x + i);
  v.x = __uint_as_float(f2tf32(v.x));
  v.y = __uint_as_float(f2tf32(v.y));
  v.z = __uint_as_float(f2tf32(v.z));
  v.w = __uint_as_float(f2tf32(v.w));
  *(float4*)(g_xC + i) = v;
}

// ============================ K1: generate W + rowsums ======================
__global__ void __launch_bounds__(256)
gen_kernel() {
  int r = blockIdx.x;
  int t = threadIdx.x;
  uint32_t base = (uint32_t)r * 8192u;
  float s = 0.0f;
#pragma unroll 1
  for (int j = 0; j < 8; j++) {
    uint32_t c = (uint32_t)t * 4u + (uint32_t)j * 1024u;
    float w0 = gibbs_weight(base + c + 0u);
    float w1 = gibbs_weight(base + c + 1u);
    float w2 = gibbs_weight(base + c + 2u);
    float w3 = gibbs_weight(base + c + 3u);
    s += (w0 + w1) + (w2 + w3);
    *(float4*)&g_W[(size_t)base + c] =
        make_float4(__uint_as_float(f2tf32(w0)), __uint_as_float(f2tf32(w1)),
                    __uint_as_float(f2tf32(w2)), __uint_as_float(f2tf32(w3)));
  }
  __shared__ float red[256];
  red[t] = s;
  __syncthreads();
#pragma unroll
  for (int o = 128; o > 0; o >>= 1) {
    if (t < o) red[t] += red[t + o];
    __syncthreads();
  }
  if (t == 0) g_rsum[r] = red[0];
}

// ============================ K2: mma.sync tf32 GEMM ========================
// CTA tile 128(M) x 128(N) x 32(K); 8 warps in 2(M) x 4(N); warp tile 64x32.
// SMEM (per stage): A[128][36] f32 (bank = 4*row+k mod 32, conflict-free)
//                   B[ 32][136] f32 (bank = 8*k+n  mod 32, conflict-free)
namespace {
constexpr int STAGES = 3;
constexpr int A_BYTES = 128 * 36 * 4;      // 18432
constexpr int B_BYTES = 32 * 136 * 4;      // 17408
constexpr int STAGE_BYTES = A_BYTES + B_BYTES;  // 35840
constexpr int SMEM_TOTAL = STAGES * STAGE_BYTES; // 107520
constexpr int NIT = 8192 / 32;             // 256
}

__global__ void __launch_bounds__(256, 1)
gemm_kernel(float* __restrict__ out) {
  extern __shared__ char smem[];
  const uint32_t sb = smem_to_u32(smem);
  const int tid = threadIdx.x;
  const int lane = tid & 31;
  const int wid = tid >> 5;
  const int g = lane >> 2;           // group id (0..7)
  const int t4 = lane & 3;           // thread-in-group (0..3)
  const int wm0 = (wid & 1) * 64;    // warp M offset in CTA tile
  const int wn0 = (wid >> 1) * 32;   // warp N offset in CTA tile
  const int m0 = blockIdx.y * 128;
  const int n0 = blockIdx.x * 128;

  float c[4][4][4];                  // [mf][nf][4]
#pragma unroll
  for (int mf = 0; mf < 4; mf++)
#pragma unroll
    for (int nf = 0; nf < 4; nf++) {
      c[mf][nf][0] = 0.f; c[mf][nf][1] = 0.f;
      c[mf][nf][2] = 0.f; c[mf][nf][3] = 0.f;
    }

  auto fill = [&](int stage, int it) {
    const int k0 = it * 32;
    const uint32_t as = sb + stage * STAGE_BYTES;
    const uint32_t bs = as + A_BYTES;
#pragma unroll
    for (int q = 0; q < 4; q++) {    // A: 128 rows x 32 K
      int idx = tid + 256 * q;
      int row = idx >> 3, c4 = idx & 7;
      const float* src = &g_W[(size_t)(m0 + row) * 8192 + k0 + c4 * 4];
      CP_ASYNC16(as + row * 144 + c4 * 16, src);
    }
#pragma unroll
    for (int q = 0; q < 4; q++) {    // B: 32 K-rows x 128 N
      int idx = tid + 256 * q;
      int kr = idx >> 5, c4 = idx & 31;
      const float* src = &g_xC[(size_t)(k0 + kr) * 1024 + n0 + c4 * 4];
      CP_ASYNC16(bs + kr * 544 + c4 * 16, src);
    }
  };

  fill(0, 0);
  asm volatile("cp.async.commit_group;" ::: "memory");
  fill(1, 1);
  asm volatile("cp.async.commit_group;" ::: "memory");

  for (int it = 0; it < NIT; ++it) {
    asm volatile("cp.async.wait_group 1;" ::: "memory");
    __syncthreads();

    const int nxt = it + STAGES - 1;
    if (nxt < NIT) fill(nxt % STAGES, nxt);
    asm volatile("cp.async.commit_group;" ::: "memory");

    const int s = it % STAGES;
    const uint32_t* As = (const uint32_t*)(smem + s * STAGE_BYTES);
    const uint32_t* Bs = (const uint32_t*)(smem + s * STAGE_BYTES + A_BYTES);

#pragma unroll
    for (int ks = 0; ks < 4; ks++) {
      const int k0 = ks * 8;
      uint32_t a[4][4];
#pragma unroll
      for (int mf = 0; mf < 4; mf++) {
        int r = wm0 + mf * 16 + g;
        a[mf][0] = As[(r    ) * 36 + k0 + t4    ];
        a[mf][1] = As[(r + 8) * 36 + k0 + t4    ];
        a[mf][2] = As[(r    ) * 36 + k0 + t4 + 4];
        a[mf][3] = As[(r + 8) * 36 + k0 + t4 + 4];
      }
      uint32_t b[4][2];
#pragma unroll
      for (int nf = 0; nf < 4; nf++) {
        int n = wn0 + nf * 8 + g;
        b[nf][0] = Bs[(k0 + t4    ) * 136 + n];
        b[nf][1] = Bs[(k0 + t4 + 4) * 136 + n];
      }
#pragma unroll
      for (int mf = 0; mf < 4; mf++)
#pragma unroll
        for (int nf = 0; nf < 4; nf++) {
          asm volatile(
              "mma.sync.aligned.m16n8k8.row.col.f32.tf32.tf32.f32 "
              "{%0,%1,%2,%3}, {%4,%5,%6,%7}, {%8,%9}, {%0,%1,%2,%3};"
              : "+f"(c[mf][nf][0]), "+f"(c[mf][nf][1]),
                "+f"(c[mf][nf][2]), "+f"(c[mf][nf][3])
              : "r"(a[mf][0]), "r"(a[mf][1]), "r"(a[mf][2]), "r"(a[mf][3]),
                "r"(b[nf][0]), "r"(b[nf][1]));
        }
    }
  }

  // ---- epilogue: divide by row sums, store ----
#pragma unroll
  for (int mf = 0; mf < 4; mf++) {
    const int r = m0 + wm0 + mf * 16 + g;
    const float inv0 = 1.0f / g_rsum[r];
    const float inv1 = 1.0f / g_rsum[r + 8];
#pragma unroll
    for (int nf = 0; nf < 4; nf++) {
      const int col = n0 + wn0 + nf * 8 + 2 * t4;
      *(float2*)(out + (size_t)r * 1024 + col) =
          make_float2(c[mf][nf][0] * inv0, c[mf][nf][1] * inv0);
      *(float2*)(out + (size_t)(r + 8) * 1024 + col) =
          make_float2(c[mf][nf][2] * inv1, c[mf][nf][3] * inv1);
    }
  }
}

// ============================ launch =======================================
extern "C" void kernel_launch(void* const* d_in, const int* in_sizes, int n_in,
                              void* d_out, int out_size) {
  (void)in_sizes; (void)n_in; (void)out_size;
  const float* x = (const float*)d_in[0];
  float* out = (float*)d_out;
  cudaFuncSetAttribute(gemm_kernel, cudaFuncAttributeMaxDynamicSharedMemorySize,
                       SMEM_TOTAL);
  xconv_kernel<<<8192, 256>>>(x);
  gen_kernel<<<8192, 256>>>();
  gemm_kernel<<<dim3(8, 64), 256, SMEM_TOTAL>>>(out);
}

// round 9
// speedup vs baseline: 4.3566x; 1.4345x over previous
#include <cuda_runtime.h>
#include <cuda_fp16.h>
#include <stdint.h>

// ---------------------------------------------------------------------------
// BoltzmannGibbsMask: out = softmax(G / 0.5, axis=1) @ x,
//   G = jax.random.normal(jax.random.key(42), (8192, 8192), f32)
// compute_103-portable plan (no 'a'-suffix features):
//   K0: transpose+convert x -> g_xT fp16 [1024][8192]
//   K1: W[r][c] = fp16(exp(2*normal(r*8192+c))) -> g_W, unrounded f32 row sums
//   K2: mma.sync.m16n8k16.f16 GEMM (f32 accum), out = (W @ x) / rowsum
// (Resubmission of R6 — previous bench aborted on container infra failure.)
// ---------------------------------------------------------------------------

static __device__ __half g_W[67108864];   // 8192*8192 fp16, 128 MB
static __device__ __half g_xT[8388608];   // 1024*8192 fp16, 16 MB (x transposed)
static __device__ float  g_rsum[8192];

// ============================ RNG (bit-exact, validated R1) =================
__device__ __forceinline__ void threefry_0_42(uint32_t x0, uint32_t x1,
                                              uint32_t& o0, uint32_t& o1) {
  const uint32_t ks0 = 0u, ks1 = 42u, ks2 = 0x1BD11BDAu ^ 42u;
  x0 += ks0; x1 += ks1;
#define TF_RND(R) { x0 += x1; x1 = __funnelshift_l(x1, x1, (R)); x1 ^= x0; }
  TF_RND(13) TF_RND(15) TF_RND(26) TF_RND(6)
  x0 += ks1; x1 += ks2 + 1u;
  TF_RND(17) TF_RND(29) TF_RND(16) TF_RND(24)
  x0 += ks2; x1 += ks0 + 2u;
  TF_RND(13) TF_RND(15) TF_RND(26) TF_RND(6)
  x0 += ks0; x1 += ks1 + 3u;
  TF_RND(17) TF_RND(29) TF_RND(16) TF_RND(24)
  x0 += ks1; x1 += ks2 + 4u;
  TF_RND(13) TF_RND(15) TF_RND(26) TF_RND(6)
  x0 += ks2; x1 += ks0 + 5u;
#undef TF_RND
  o0 = x0; o1 = x1;
}

__device__ __forceinline__ float erfinv_xla(float x) {
  float w = -log1pf(-x * x);
  float p;
  if (w < 5.0f) {
    w = w - 2.5f;
    p = 2.81022636e-08f;
    p = fmaf(p, w, 3.43273939e-07f);
    p = fmaf(p, w, -3.5233877e-06f);
    p = fmaf(p, w, -4.39150654e-06f);
    p = fmaf(p, w, 0.00021858087f);
    p = fmaf(p, w, -0.00125372503f);
    p = fmaf(p, w, -0.00417768164f);
    p = fmaf(p, w, 0.246640727f);
    p = fmaf(p, w, 1.50140941f);
  } else {
    w = sqrtf(w) - 3.0f;
    p = -0.000200214257f;
    p = fmaf(p, w, 0.000100950558f);
    p = fmaf(p, w, 0.00134934322f);
    p = fmaf(p, w, -0.00367342844f);
    p = fmaf(p, w, 0.00573950773f);
    p = fmaf(p, w, -0.0076224613f);
    p = fmaf(p, w, 0.00943887047f);
    p = fmaf(p, w, 1.00167406f);
    p = fmaf(p, w, 2.83297682f);
  }
  return p * x;
}

__device__ __forceinline__ float gibbs_weight(uint32_t idx) {
  uint32_t o0, o1;
  threefry_0_42(0u, idx, o0, o1);
  uint32_t bits = o0 ^ o1;
  float f = __uint_as_float((bits >> 9) | 0x3f800000u);
  f = __fadd_rn(f, -1.0f);
  const float lo = -0.99999994f;
  float u = __fadd_rn(__fmul_rn(f, 2.0f), lo);
  u = fmaxf(lo, u);
  float m = 1.41421356237f * erfinv_xla(u);
  return __expf(__fmul_rn(m, 2.0f));
}

// ============================ helpers ======================================
__device__ __forceinline__ uint32_t smem_to_u32(const void* p) {
  uint32_t a;
  asm("{ .reg .u64 t; cvta.to.shared.u64 t, %1; cvt.u32.u64 %0, t; }"
      : "=r"(a) : "l"(p));
  return a;
}
#define CP_ASYNC16(dst, src) \
  asm volatile("cp.async.cg.shared.global [%0], [%1], 16;" \
               :: "r"(dst), "l"(src) : "memory")

// ============================ K0: transpose + cvt x =========================
__global__ void __launch_bounds__(256)
transpose_cvt_kernel(const float* __restrict__ x) {
  __shared__ float tile[32][33];
  int tx = threadIdx.x, ty = threadIdx.y;
  int n0 = blockIdx.x * 32;           // over D=1024
  int k0 = blockIdx.y * 32;           // over N=8192
#pragma unroll
  for (int i = 0; i < 4; i++)
    tile[ty + i * 8][tx] = x[(size_t)(k0 + ty + i * 8) * 1024 + n0 + tx];
  __syncthreads();
#pragma unroll
  for (int i = 0; i < 4; i++)
    g_xT[(size_t)(n0 + ty + i * 8) * 8192 + k0 + tx] =
        __float2half_rn(tile[tx][ty + i * 8]);
}

// ============================ K1: generate W + rowsums ======================
__global__ void __launch_bounds__(256)
gen_kernel() {
  int r = blockIdx.x;
  int t = threadIdx.x;
  uint32_t base = (uint32_t)r * 8192u;
  float s = 0.0f;
#pragma unroll 1
  for (int j = 0; j < 8; j++) {
    uint32_t c = (uint32_t)t * 4u + (uint32_t)j * 1024u;
    float w0 = gibbs_weight(base + c + 0u);
    float w1 = gibbs_weight(base + c + 1u);
    float w2 = gibbs_weight(base + c + 2u);
    float w3 = gibbs_weight(base + c + 3u);
    s += (w0 + w1) + (w2 + w3);
    __half2 h01 = make_half2(__float2half_rn(w0), __float2half_rn(w1));
    __half2 h23 = make_half2(__float2half_rn(w2), __float2half_rn(w3));
    uint2 pk;
    pk.x = *(uint32_t*)&h01;
    pk.y = *(uint32_t*)&h23;
    *(uint2*)&g_W[(size_t)base + c] = pk;
  }
  __shared__ float red[256];
  red[t] = s;
  __syncthreads();
#pragma unroll
  for (int o = 128; o > 0; o >>= 1) {
    if (t < o) red[t] += red[t + o];
    __syncthreads();
  }
  if (t == 0) g_rsum[r] = red[0];
}

// ============================ K2: mma.sync fp16 GEMM ========================
// CTA tile 128(M) x 128(N) x 32(K); 8 warps 2(M)x4(N); warp tile 64x32.
// SMEM rows padded to 40 fp16 (20 b32 words): bank(20g+t4) bijective -> no
// conflicts on fragment loads (A and B use identical layout).
namespace {
constexpr int STAGES = 4;
constexpr int ROW_H = 40;                      // fp16 per padded row
constexpr int ROW_B = ROW_H * 2;               // 80 bytes
constexpr int ROW_W = ROW_H / 2;               // 20 b32 words
constexpr int A_BYTES = 128 * ROW_B;           // 10240
constexpr int B_BYTES = 128 * ROW_B;           // 10240
constexpr int STAGE_BYTES = A_BYTES + B_BYTES; // 20480
constexpr int SMEM_TOTAL = STAGES * STAGE_BYTES; // 81920
constexpr int NIT = 8192 / 32;                 // 256
}

__global__ void __launch_bounds__(256, 1)
gemm_kernel(float* __restrict__ out) {
  extern __shared__ char smem[];
  const uint32_t sb = smem_to_u32(smem);
  const int tid = threadIdx.x;
  const int lane = tid & 31;
  const int wid = tid >> 5;
  const int g = lane >> 2;           // group id (0..7)
  const int t4 = lane & 3;           // thread-in-group (0..3)
  const int wm0 = (wid & 1) * 64;    // warp M offset
  const int wn0 = (wid >> 1) * 32;   // warp N offset
  const int m0 = blockIdx.y * 128;
  const int n0 = blockIdx.x * 128;

  float c[4][4][4];
#pragma unroll
  for (int mf = 0; mf < 4; mf++)
#pragma unroll
    for (int nf = 0; nf < 4; nf++) {
      c[mf][nf][0] = 0.f; c[mf][nf][1] = 0.f;
      c[mf][nf][2] = 0.f; c[mf][nf][3] = 0.f;
    }

  auto fill = [&](int stage, int it) {
    const int k0 = it * 32;
    const uint32_t as = sb + stage * STAGE_BYTES;
    const uint32_t bs = as + A_BYTES;
    // A: 128 rows x 32 fp16 = 4 x 16B chunks per row -> 512 chunks
#pragma unroll
    for (int q = 0; q < 2; q++) {
      int idx = tid + 256 * q;
      int row = idx >> 2, c4 = idx & 3;
      const __half* src = &g_W[(size_t)(m0 + row) * 8192 + k0 + c4 * 8];
      CP_ASYNC16(as + row * ROW_B + c4 * 16, src);
    }
    // B: 128 n-rows x 32 fp16 (k-contiguous from g_xT)
#pragma unroll
    for (int q = 0; q < 2; q++) {
      int idx = tid + 256 * q;
      int row = idx >> 2, c4 = idx & 3;
      const __half* src = &g_xT[(size_t)(n0 + row) * 8192 + k0 + c4 * 8];
      CP_ASYNC16(bs + row * ROW_B + c4 * 16, src);
    }
  };

  fill(0, 0);
  asm volatile("cp.async.commit_group;" ::: "memory");
  fill(1, 1);
  asm volatile("cp.async.commit_group;" ::: "memory");
  fill(2, 2);
  asm volatile("cp.async.commit_group;" ::: "memory");

  for (int it = 0; it < NIT; ++it) {
    asm volatile("cp.async.wait_group 2;" ::: "memory");
    __syncthreads();

    const int nxt = it + STAGES - 1;
    if (nxt < NIT) fill(nxt % STAGES, nxt);
    asm volatile("cp.async.commit_group;" ::: "memory");

    const int s = it % STAGES;
    const uint32_t* As = (const uint32_t*)(smem + s * STAGE_BYTES);
    const uint32_t* Bs = (const uint32_t*)(smem + s * STAGE_BYTES + A_BYTES);

#pragma unroll
    for (int ks = 0; ks < 2; ks++) {             // two k16 steps per stage
      const int kw = ks * 8;                     // word offset of k16 block
      uint32_t a[4][4];
#pragma unroll
      for (int mf = 0; mf < 4; mf++) {
        int r = wm0 + mf * 16 + g;
        a[mf][0] = As[(r    ) * ROW_W + kw + t4    ];
        a[mf][1] = As[(r + 8) * ROW_W + kw + t4    ];
        a[mf][2] = As[(r    ) * ROW_W + kw + t4 + 4];
        a[mf][3] = As[(r + 8) * ROW_W + kw + t4 + 4];
      }
      uint32_t b[4][2];
#pragma unroll
      for (int nf = 0; nf < 4; nf++) {
        int n = wn0 + nf * 8 + g;
        b[nf][0] = Bs[n * ROW_W + kw + t4    ];
        b[nf][1] = Bs[n * ROW_W + kw + t4 + 4];
      }
#pragma unroll
      for (int mf = 0; mf < 4; mf++)
#pragma unroll
        for (int nf = 0; nf < 4; nf++) {
          asm volatile(
              "mma.sync.aligned.m16n8k16.row.col.f32.f16.f16.f32 "
              "{%0,%1,%2,%3}, {%4,%5,%6,%7}, {%8,%9}, {%0,%1,%2,%3};"
              : "+f"(c[mf][nf][0]), "+f"(c[mf][nf][1]),
                "+f"(c[mf][nf][2]), "+f"(c[mf][nf][3])
              : "r"(a[mf][0]), "r"(a[mf][1]), "r"(a[mf][2]), "r"(a[mf][3]),
                "r"(b[nf][0]), "r"(b[nf][1]));
        }
    }
  }

  // ---- epilogue: divide by row sums, store ----
#pragma unroll
  for (int mf = 0; mf < 4; mf++) {
    const int r = m0 + wm0 + mf * 16 + g;
    const float inv0 = 1.0f / g_rsum[r];
    const float inv1 = 1.0f / g_rsum[r + 8];
#pragma unroll
    for (int nf = 0; nf < 4; nf++) {
      const int col = n0 + wn0 + nf * 8 + 2 * t4;
      *(float2*)(out + (size_t)r * 1024 + col) =
          make_float2(c[mf][nf][0] * inv0, c[mf][nf][1] * inv0);
      *(float2*)(out + (size_t)(r + 8) * 1024 + col) =
          make_float2(c[mf][nf][2] * inv1, c[mf][nf][3] * inv1);
    }
  }
}

// ============================ launch =======================================
extern "C" void kernel_launch(void* const* d_in, const int* in_sizes, int n_in,
                              void* d_out, int out_size) {
  (void)in_sizes; (void)n_in; (void)out_size;
  const float* x = (const float*)d_in[0];
  float* out = (float*)d_out;
  cudaFuncSetAttribute(gemm_kernel, cudaFuncAttributeMaxDynamicSharedMemorySize,
                       SMEM_TOTAL);
  transpose_cvt_kernel<<<dim3(32, 256), dim3(32, 8)>>>(x);
  gen_kernel<<<8192, 256>>>();
  gemm_kernel<<<dim3(8, 64), 256, SMEM_TOTAL>>>(out);
}